// round 1
// baseline (speedup 1.0000x reference)
#include <cuda_runtime.h>
#include <math.h>

// ---------------- problem constants ----------------
#define BB   4
#define SEQ  2048
#define CDIM 1024
#define NH   16
#define HD   64
#define MROWS (BB*SEQ)          // 8192

// ---------------- scratch (device globals; no allocations allowed) ----------
__device__ float g_Q[BB*NH*SEQ*HD];   // [B,H,N,D]
__device__ float g_K[BB*NH*SEQ*HD];
__device__ float g_V[BB*NH*SEQ*HD];
__device__ float g_O[BB*SEQ*NH*HD];   // [B,N,H,D] == [8192,1024]

// ---------------- f32x2 packed-FMA helpers (Blackwell fp32x2 pipe) ---------
typedef unsigned long long ull;

__device__ __forceinline__ ull ffma2(ull a, ull b, ull c) {
    ull d;
    asm("fma.rn.f32x2 %0, %1, %2, %3;" : "=l"(d) : "l"(a), "l"(b), "l"(c));
    return d;
}
__device__ __forceinline__ ull fmul2(ull a, ull b) {
    ull d;
    asm("mul.rn.f32x2 %0, %1, %2;" : "=l"(d) : "l"(a), "l"(b));
    return d;
}
__device__ __forceinline__ ull pack2(float lo, float hi) {
    ull r;
    asm("mov.b64 %0, {%1, %2};" : "=l"(r) : "f"(lo), "f"(hi));
    return r;
}
__device__ __forceinline__ float2 unpack2(ull v) {
    float lo, hi;
    asm("mov.b64 {%0, %1}, %2;" : "=f"(lo), "=f"(hi) : "l"(v));
    return make_float2(lo, hi);
}

union F4U2 {
    float4 f4;
    ull    u[2];
};

// ---------------- QKV scatter helper ----------------------------------------
__device__ __forceinline__ void qkv_scatter(int row, int col, float val) {
    // row in [0, 8192): b = row>>11, n = row & 2047
    // col in [0, 3072): part = col>>10, h = (col&1023)>>6, d = col&63
    int part = col >> 10;
    int rem  = col & 1023;
    int h    = rem >> 6;
    int d    = rem & 63;
    int b    = row >> 11;
    int n    = row & 2047;
    float* dst = (part == 0) ? g_Q : (part == 1) ? g_K : g_V;
    dst[(((b << 4) + h) * SEQ + n) * HD + d] = val;
}

// ---------------- SGEMM: C[M,N] = A[M,K] @ B[K,N] + bias --------------------
// BM=128, BN=128, BK=16, TM=8, TN=8, 256 threads.
// MODE 0: A = x, scatter into g_Q/g_K/g_V (bias = b_qkv)
// MODE 1: A = g_O, write Cout row-major (bias = b_proj)
template <int MODE>
__global__ __launch_bounds__(256, 2)
void sgemm_kernel(const float* __restrict__ A,
                  const float* __restrict__ Bm,
                  const float* __restrict__ bias,
                  float* __restrict__ Cout,
                  int Mdim, int Ndim, int Kdim)
{
    __shared__ __align__(16) float As[16][132];   // transposed, padded
    __shared__ __align__(16) float Bs[16][128];

    const int tid  = threadIdx.x;
    const int cCol = blockIdx.x;   // N tile
    const int cRow = blockIdx.y;   // M tile
    const int tRow = tid >> 4;     // 0..15
    const int tCol = tid & 15;     // 0..15

    const float* Ap = (MODE == 1) ? &g_O[0] : A;

    // A-tile load mapping: 128 rows x 4 float4-cols; each thread: 2 rows
    const int aRow = tid >> 2;     // 0..63
    const int aCol = tid & 3;      // 0..3 (float4 index along K)
    // B-tile load mapping: 16 k-rows x 32 float4-cols; each thread: 2 k-rows
    const int bRow = tid >> 5;     // 0..7
    const int bCol = tid & 31;     // 0..31

    ull acc[8][4];
    #pragma unroll
    for (int i = 0; i < 8; i++)
        #pragma unroll
        for (int j = 0; j < 4; j++) acc[i][j] = 0ull;

    const int ktiles = Kdim >> 4;
    #pragma unroll 1
    for (int kt = 0; kt < ktiles; ++kt) {
        // load A tile (transposed into As[k][m])
        #pragma unroll
        for (int rr = 0; rr < 2; rr++) {
            int r = aRow + rr * 64;
            float4 v = *(const float4*)&Ap[(size_t)(cRow * 128 + r) * Kdim + kt * 16 + aCol * 4];
            As[aCol * 4 + 0][r] = v.x;
            As[aCol * 4 + 1][r] = v.y;
            As[aCol * 4 + 2][r] = v.z;
            As[aCol * 4 + 3][r] = v.w;
        }
        // load B tile
        #pragma unroll
        for (int rr = 0; rr < 2; rr++) {
            int kr = bRow + rr * 8;
            *(float4*)&Bs[kr][bCol * 4] =
                *(const float4*)&Bm[(size_t)(kt * 16 + kr) * Ndim + cCol * 128 + bCol * 4];
        }
        __syncthreads();

        #pragma unroll
        for (int kk = 0; kk < 16; kk++) {
            float4 a0 = *(const float4*)&As[kk][tRow * 8];
            float4 a1 = *(const float4*)&As[kk][tRow * 8 + 4];
            F4U2 b0, b1;
            b0.f4 = *(const float4*)&Bs[kk][tCol * 8];
            b1.f4 = *(const float4*)&Bs[kk][tCol * 8 + 4];
            ull bb[4] = { b0.u[0], b0.u[1], b1.u[0], b1.u[1] };
            float av[8] = { a0.x, a0.y, a0.z, a0.w, a1.x, a1.y, a1.z, a1.w };
            #pragma unroll
            for (int i = 0; i < 8; i++) {
                ull a2 = pack2(av[i], av[i]);
                #pragma unroll
                for (int j = 0; j < 4; j++)
                    acc[i][j] = ffma2(a2, bb[j], acc[i][j]);
            }
        }
        __syncthreads();
    }

    const int row0 = cRow * 128 + tRow * 8;
    const int col0 = cCol * 128 + tCol * 8;

    if (MODE == 0) {
        #pragma unroll
        for (int i = 0; i < 8; i++) {
            #pragma unroll
            for (int j = 0; j < 4; j++) {
                float2 v = unpack2(acc[i][j]);
                int c0 = col0 + 2 * j;
                qkv_scatter(row0 + i, c0,     v.x + __ldg(&bias[c0]));
                qkv_scatter(row0 + i, c0 + 1, v.y + __ldg(&bias[c0 + 1]));
            }
        }
    } else {
        float4 bv0 = *(const float4*)&bias[col0];
        float4 bv1 = *(const float4*)&bias[col0 + 4];
        #pragma unroll
        for (int i = 0; i < 8; i++) {
            float2 p0 = unpack2(acc[i][0]);
            float2 p1 = unpack2(acc[i][1]);
            float2 p2 = unpack2(acc[i][2]);
            float2 p3 = unpack2(acc[i][3]);
            float4 w0 = make_float4(p0.x + bv0.x, p0.y + bv0.y, p1.x + bv0.z, p1.y + bv0.w);
            float4 w1 = make_float4(p2.x + bv1.x, p2.y + bv1.y, p3.x + bv1.z, p3.y + bv1.w);
            size_t base = (size_t)(row0 + i) * Ndim + col0;
            *(float4*)&Cout[base]     = w0;
            *(float4*)&Cout[base + 4] = w1;
        }
    }
}

// ---------------- flash attention (fp32, 1 query row per thread) -----------
// grid: (SEQ/128, B*H); 128 threads; K/V tiles of 32 rows in SMEM.
__global__ __launch_bounds__(128, 2)
void attn_kernel()
{
    __shared__ __align__(16) float Ks[32][64];
    __shared__ __align__(16) float Vs[32][64];

    const int tid  = threadIdx.x;
    const int bh   = blockIdx.y;
    const int qrow = blockIdx.x * 128 + tid;

    const float* Qb = g_Q + (size_t)bh * (SEQ * HD);
    const float* Kb = g_K + (size_t)bh * (SEQ * HD);
    const float* Vb = g_V + (size_t)bh * (SEQ * HD);

    // q row into registers, pre-scaled by 1/sqrt(D) = 0.125
    ull q2[32];
    {
        const float4* qp = (const float4*)(Qb + (size_t)qrow * HD);
        #pragma unroll
        for (int i = 0; i < 16; i++) {
            float4 v = qp[i];
            q2[2 * i]     = pack2(v.x * 0.125f, v.y * 0.125f);
            q2[2 * i + 1] = pack2(v.z * 0.125f, v.w * 0.125f);
        }
    }

    ull o2[32];
    #pragma unroll
    for (int i = 0; i < 32; i++) o2[i] = 0ull;
    float m = -1e30f, l = 0.0f;

    #pragma unroll 1
    for (int kt = 0; kt < SEQ / 32; ++kt) {
        // cooperative coalesced K/V tile load: 32x64 floats each
        {
            const float4* ksrc = (const float4*)(Kb + (size_t)kt * 32 * HD);
            const float4* vsrc = (const float4*)(Vb + (size_t)kt * 32 * HD);
            float4* kdst = (float4*)&Ks[0][0];
            float4* vdst = (float4*)&Vs[0][0];
            #pragma unroll
            for (int i = 0; i < 4; i++) {
                kdst[tid + 128 * i] = ksrc[tid + 128 * i];
                vdst[tid + 128 * i] = vsrc[tid + 128 * i];
            }
        }
        __syncthreads();

        // S = q . K[j]  (already scaled)
        float s[32];
        #pragma unroll
        for (int j = 0; j < 32; j++) {
            const float4* kp = (const float4*)&Ks[j][0];
            ull a0 = 0, a1 = 0, a2 = 0, a3 = 0;
            #pragma unroll
            for (int i = 0; i < 4; i++) {
                F4U2 t0, t1, t2, t3;
                t0.f4 = kp[4 * i + 0];
                t1.f4 = kp[4 * i + 1];
                t2.f4 = kp[4 * i + 2];
                t3.f4 = kp[4 * i + 3];
                a0 = ffma2(q2[8 * i + 0], t0.u[0], a0);
                a1 = ffma2(q2[8 * i + 1], t0.u[1], a1);
                a2 = ffma2(q2[8 * i + 2], t1.u[0], a2);
                a3 = ffma2(q2[8 * i + 3], t1.u[1], a3);
                a0 = ffma2(q2[8 * i + 4], t2.u[0], a0);
                a1 = ffma2(q2[8 * i + 5], t2.u[1], a1);
                a2 = ffma2(q2[8 * i + 6], t3.u[0], a2);
                a3 = ffma2(q2[8 * i + 7], t3.u[1], a3);
            }
            float2 r0 = unpack2(a0), r1 = unpack2(a1);
            float2 r2 = unpack2(a2), r3 = unpack2(a3);
            s[j] = ((r0.x + r0.y) + (r1.x + r1.y)) + ((r2.x + r2.y) + (r3.x + r3.y));
        }

        // online softmax
        float mt = m;
        #pragma unroll
        for (int j = 0; j < 32; j++) mt = fmaxf(mt, s[j]);
        float corr = __expf(m - mt);
        m = mt;
        l *= corr;
        ull c2 = pack2(corr, corr);
        #pragma unroll
        for (int i = 0; i < 32; i++) o2[i] = fmul2(o2[i], c2);

        #pragma unroll
        for (int j = 0; j < 32; j++) {
            float p = __expf(s[j] - m);
            l += p;
            ull p2 = pack2(p, p);
            const float4* vp = (const float4*)&Vs[j][0];
            #pragma unroll
            for (int i = 0; i < 8; i++) {
                F4U2 t0, t1;
                t0.f4 = vp[2 * i];
                t1.f4 = vp[2 * i + 1];
                o2[4 * i + 0] = ffma2(p2, t0.u[0], o2[4 * i + 0]);
                o2[4 * i + 1] = ffma2(p2, t0.u[1], o2[4 * i + 1]);
                o2[4 * i + 2] = ffma2(p2, t1.u[0], o2[4 * i + 2]);
                o2[4 * i + 3] = ffma2(p2, t1.u[1], o2[4 * i + 3]);
            }
        }
        __syncthreads();
    }

    // write O in [B, N, H, D] layout
    float inv = 1.0f / l;
    int b = bh >> 4;
    int h = bh & 15;
    float* op = g_O + (((size_t)b * SEQ + qrow) * NH + h) * HD;
    #pragma unroll
    for (int i = 0; i < 8; i++) {
        float2 v0 = unpack2(o2[4 * i + 0]);
        float2 v1 = unpack2(o2[4 * i + 1]);
        float2 v2 = unpack2(o2[4 * i + 2]);
        float2 v3 = unpack2(o2[4 * i + 3]);
        float4 w0 = make_float4(v0.x * inv, v0.y * inv, v1.x * inv, v1.y * inv);
        float4 w1 = make_float4(v2.x * inv, v2.y * inv, v3.x * inv, v3.y * inv);
        ((float4*)op)[2 * i]     = w0;
        ((float4*)op)[2 * i + 1] = w1;
    }
}

// ---------------- launch -----------------------------------------------------
extern "C" void kernel_launch(void* const* d_in, const int* in_sizes, int n_in,
                              void* d_out, int out_size)
{
    const float* x      = (const float*)d_in[0];
    const float* W_qkv  = (const float*)d_in[1];
    const float* b_qkv  = (const float*)d_in[2];
    const float* W_proj = (const float*)d_in[3];
    const float* b_proj = (const float*)d_in[4];
    float* out = (float*)d_out;

    // 1) QKV GEMM + scatter: [8192,1024] @ [1024,3072]
    dim3 g1(3 * CDIM / 128, MROWS / 128);      // (24, 64)
    sgemm_kernel<0><<<g1, 256>>>(x, W_qkv, b_qkv, nullptr, MROWS, 3 * CDIM, CDIM);

    // 2) attention
    dim3 ga(SEQ / 128, BB * NH);               // (16, 64)
    attn_kernel<<<ga, 128>>>();

    // 3) output projection: [8192,1024] @ [1024,1024]
    dim3 g2(CDIM / 128, MROWS / 128);          // (8, 64)
    sgemm_kernel<1><<<g2, 256>>>(nullptr, W_proj, b_proj, out, MROWS, CDIM, CDIM);
}

// round 3
// speedup vs baseline: 1.2817x; 1.2817x over previous
#include <cuda_runtime.h>
#include <cuda_bf16.h>
#include <cstdint>
#include <math.h>

// ---------------- problem constants ----------------
#define BB   4
#define SEQ  2048
#define CDIM 1024
#define NH   16
#define HD   64
#define MROWS (BB*SEQ)          // 8192
#define KDIM 1024
#define NQKV 3072
#define BK   32
#define PADK 40                 // padded smem row (bf16 elems): conflict-free ldmatrix
#define NCHUNK 96               // K' = 3*1024 / 32

// ---------------- scratch (device globals) ----------------
__device__ float g_Q[BB*NH*SEQ*HD];   // [B,H,N,D] fp32
__device__ float g_K[BB*NH*SEQ*HD];
__device__ float g_V[BB*NH*SEQ*HD];
__device__ __nv_bfloat16 g_Ahi[MROWS*KDIM];
__device__ __nv_bfloat16 g_Alo[MROWS*KDIM];
__device__ __nv_bfloat16 g_Ohi[MROWS*CDIM];   // attention out split, [B,N,H*D]
__device__ __nv_bfloat16 g_Olo[MROWS*CDIM];
__device__ __nv_bfloat16 g_Wqhi[NQKV*KDIM];   // W_qkv^T split, [N,K]
__device__ __nv_bfloat16 g_Wqlo[NQKV*KDIM];
__device__ __nv_bfloat16 g_Wphi[CDIM*KDIM];   // W_proj^T split, [N,K]
__device__ __nv_bfloat16 g_Wplo[CDIM*KDIM];

// ---------------- helpers ----------------
typedef unsigned long long ull;

__device__ __forceinline__ uint32_t smem_u32(const void* p) {
    return (uint32_t)__cvta_generic_to_shared(p);
}
__device__ __forceinline__ ull ffma2(ull a, ull b, ull c) {
    ull d; asm("fma.rn.f32x2 %0, %1, %2, %3;" : "=l"(d) : "l"(a), "l"(b), "l"(c)); return d;
}
__device__ __forceinline__ ull fmul2(ull a, ull b) {
    ull d; asm("mul.rn.f32x2 %0, %1, %2;" : "=l"(d) : "l"(a), "l"(b)); return d;
}
__device__ __forceinline__ ull pack2(float lo, float hi) {
    ull r; asm("mov.b64 %0, {%1, %2};" : "=l"(r) : "f"(lo), "f"(hi)); return r;
}
__device__ __forceinline__ float2 unpack2(ull v) {
    float lo, hi; asm("mov.b64 {%0, %1}, %2;" : "=f"(lo), "=f"(hi) : "l"(v));
    return make_float2(lo, hi);
}
union F4U2 { float4 f4; ull u[2]; };

__device__ __forceinline__ void cp16(uint32_t dst, const void* src) {
    asm volatile("cp.async.cg.shared.global [%0], [%1], 16;" :: "r"(dst), "l"(src));
}
__device__ __forceinline__ void cp_commit() {
    asm volatile("cp.async.commit_group;");
}
__device__ __forceinline__ void ldm_x4(uint32_t* r, uint32_t addr) {
    asm volatile("ldmatrix.sync.aligned.m8n8.x4.shared.b16 {%0,%1,%2,%3}, [%4];"
                 : "=r"(r[0]), "=r"(r[1]), "=r"(r[2]), "=r"(r[3]) : "r"(addr));
}
__device__ __forceinline__ void mma16816(float* c, const uint32_t* a, const uint32_t* b) {
    asm volatile(
        "mma.sync.aligned.m16n8k16.row.col.f32.bf16.bf16.f32 "
        "{%0,%1,%2,%3}, {%4,%5,%6,%7}, {%8,%9}, {%0,%1,%2,%3};"
        : "+f"(c[0]), "+f"(c[1]), "+f"(c[2]), "+f"(c[3])
        : "r"(a[0]), "r"(a[1]), "r"(a[2]), "r"(a[3]), "r"(b[0]), "r"(b[1]));
}

// ---------------- conversion kernels (write fixed globals) ----------------
__global__ void conv_split(const float* __restrict__ src, int n4)
{
    int i = blockIdx.x * blockDim.x + threadIdx.x;
    if (i >= n4) return;
    float4 v = ((const float4*)src)[i];
    union { uint2 u; __nv_bfloat16 h[4]; } ph, pl;
    float vv[4] = { v.x, v.y, v.z, v.w };
    #pragma unroll
    for (int k = 0; k < 4; k++) {
        __nv_bfloat16 h = __float2bfloat16(vv[k]);
        ph.h[k] = h;
        pl.h[k] = __float2bfloat16(vv[k] - __bfloat162float(h));
    }
    ((uint2*)g_Ahi)[i] = ph.u;
    ((uint2*)g_Alo)[i] = pl.u;
}

// transpose + split: W[K,N] row-major -> [N,K]; SEL 0 -> Wq, 1 -> Wp
template <int SEL>
__global__ void conv_wT(const float* __restrict__ W, int Nd)
{
    __shared__ float t[32][33];
    __nv_bfloat16* hi = SEL ? g_Wphi : g_Wqhi;
    __nv_bfloat16* lo = SEL ? g_Wplo : g_Wqlo;
    int n0 = blockIdx.x * 32, k0 = blockIdx.y * 32;
    #pragma unroll
    for (int i = 0; i < 4; i++) {
        int k = k0 + threadIdx.y + i * 8;
        t[threadIdx.y + i * 8][threadIdx.x] = W[(size_t)k * Nd + n0 + threadIdx.x];
    }
    __syncthreads();
    #pragma unroll
    for (int i = 0; i < 4; i++) {
        int n = n0 + threadIdx.y + i * 8;
        int k = k0 + threadIdx.x;
        float v = t[threadIdx.x][threadIdx.y + i * 8];
        __nv_bfloat16 h = __float2bfloat16(v);
        hi[(size_t)n * KDIM + k] = h;
        lo[(size_t)n * KDIM + k] = __float2bfloat16(v - __bfloat162float(h));
    }
}

// ---------------- split-bf16 GEMM on mma.sync (HMMA) ----------------
// C[M,N] = A[M,K] x B[N,K]^T, K' = 3K via segments (AhiBhi + AloBhi + AhiBlo).
// 128x128 tile, BK=32, 8 warps (2 M x 4 N), warp tile 64x32.
// MODE 0: A = x split, B = Wq split, scatter to g_Q/K/V + b_qkv.
// MODE 1: A = O split, B = Wp split, write out + b_proj.
template <int MODE>
__global__ __launch_bounds__(256)
void mma_gemm(const float* __restrict__ bias, float* __restrict__ out)
{
    constexpr int Ndim = (MODE == 0) ? NQKV : CDIM;
    __shared__ __align__(16) __nv_bfloat16 As[2][128 * PADK];
    __shared__ __align__(16) __nv_bfloat16 Bs[2][128 * PADK];

    const __nv_bfloat16* Ahi = (MODE == 0) ? g_Ahi : g_Ohi;
    const __nv_bfloat16* Alo = (MODE == 0) ? g_Alo : g_Olo;
    const __nv_bfloat16* Bhi = (MODE == 0) ? g_Wqhi : g_Wphi;
    const __nv_bfloat16* Blo = (MODE == 0) ? g_Wqlo : g_Wplo;

    const int tid = threadIdx.x;
    const int lane = tid & 31, wid = tid >> 5;
    const int warp_m = wid >> 2, warp_n = wid & 3;
    const int mTile = blockIdx.y, nTile = blockIdx.x;
    const int aRow0 = mTile * 128, bRow0 = nTile * 128;

    const int lrow = tid >> 2;   // 0..63
    const int lseg = tid & 3;    // 0..3

    const uint32_t asBase = smem_u32(&As[0][0]);
    const uint32_t bsBase = smem_u32(&Bs[0][0]);
    const uint32_t stageBytes = 128 * PADK * 2;

    auto load_chunk = [&](int kc) {
        int seg = kc >> 5;
        int k0  = (kc & 31) * BK;
        const __nv_bfloat16* Ap = (seg == 1) ? Alo : Ahi;
        const __nv_bfloat16* Bp = (seg == 2) ? Blo : Bhi;
        uint32_t so = (uint32_t)(kc & 1) * stageBytes;
        #pragma unroll
        for (int i = 0; i < 2; i++) {
            int row = lrow + 64 * i;
            uint32_t doff = so + (uint32_t)row * (PADK * 2) + (uint32_t)lseg * 16;
            cp16(asBase + doff, Ap + (size_t)(aRow0 + row) * KDIM + k0 + lseg * 8);
            cp16(bsBase + doff, Bp + (size_t)(bRow0 + row) * KDIM + k0 + lseg * 8);
        }
        cp_commit();
    };

    float acc[4][4][4];
    #pragma unroll
    for (int mi = 0; mi < 4; mi++)
        #pragma unroll
        for (int ni = 0; ni < 4; ni++)
            #pragma unroll
            for (int q = 0; q < 4; q++) acc[mi][ni][q] = 0.0f;

    load_chunk(0);
    load_chunk(1);

    // per-thread ldmatrix relative offsets
    const int aRowL = warp_m * 64 + (lane & 15);
    const int aKoff = (lane >> 4) << 3;
    const int bRowL = warp_n * 32 + ((lane >> 4) << 3) + (lane & 7);
    const int bKoff = ((lane >> 3) & 1) << 3;

    #pragma unroll 1
    for (int kc = 0; kc < NCHUNK; ++kc) {
        if (kc == NCHUNK - 1) asm volatile("cp.async.wait_group 0;" ::: "memory");
        else                  asm volatile("cp.async.wait_group 1;" ::: "memory");
        __syncthreads();

        uint32_t ab = asBase + (uint32_t)(kc & 1) * stageBytes;
        uint32_t bb = bsBase + (uint32_t)(kc & 1) * stageBytes;

        #pragma unroll
        for (int ks = 0; ks < 2; ks++) {
            uint32_t a_r[4][4];
            uint32_t b_r[4][2];
            #pragma unroll
            for (int mi = 0; mi < 4; mi++) {
                uint32_t addr = ab + (uint32_t)(aRowL + mi * 16) * (PADK * 2)
                              + (uint32_t)(ks * 16 + aKoff) * 2;
                ldm_x4(a_r[mi], addr);
            }
            #pragma unroll
            for (int np = 0; np < 2; np++) {
                uint32_t addr = bb + (uint32_t)(bRowL + np * 16) * (PADK * 2)
                              + (uint32_t)(ks * 16 + bKoff) * 2;
                uint32_t r[4];
                ldm_x4(r, addr);
                b_r[np * 2][0]     = r[0];
                b_r[np * 2][1]     = r[1];
                b_r[np * 2 + 1][0] = r[2];
                b_r[np * 2 + 1][1] = r[3];
            }
            #pragma unroll
            for (int mi = 0; mi < 4; mi++)
                #pragma unroll
                for (int ni = 0; ni < 4; ni++)
                    mma16816(acc[mi][ni], a_r[mi], b_r[ni]);
        }
        __syncthreads();
        if (kc + 2 < NCHUNK) load_chunk(kc + 2);
    }

    // ---------------- epilogue ----------------
    const int mBase = mTile * 128 + warp_m * 64;
    const int nBase = nTile * 128 + warp_n * 32;
    const int rq = lane >> 2;
    const int cq = (lane & 3) * 2;

    #pragma unroll
    for (int mi = 0; mi < 4; mi++) {
        #pragma unroll
        for (int ni = 0; ni < 4; ni++) {
            int col = nBase + ni * 8 + cq;
            float2 bv = *(const float2*)&bias[col];
            #pragma unroll
            for (int h2 = 0; h2 < 2; h2++) {
                int row = mBase + mi * 16 + rq + h2 * 8;
                float2 v = make_float2(acc[mi][ni][h2 * 2]     + bv.x,
                                       acc[mi][ni][h2 * 2 + 1] + bv.y);
                if (MODE == 0) {
                    int part = col >> 10;
                    float* dst = (part == 0) ? g_Q : (part == 1) ? g_K : g_V;
                    int b = row >> 11, n = row & 2047;
                    int h = (col & 1023) >> 6, d = col & 63;
                    *(float2*)&dst[(((size_t)(b * NH + h)) * SEQ + n) * HD + d] = v;
                } else {
                    *(float2*)&out[(size_t)row * Ndim + col] = v;
                }
            }
        }
    }
}

// ---------------- flash attention (fp32 SIMT; split-bf16 output) ----------
__global__ __launch_bounds__(128, 2)
void attn_kernel()
{
    __shared__ __align__(16) float Ks[32][64];
    __shared__ __align__(16) float Vs[32][64];

    const int tid  = threadIdx.x;
    const int bh   = blockIdx.y;
    const int qrow = blockIdx.x * 128 + tid;

    const float* Qb = g_Q + (size_t)bh * (SEQ * HD);
    const float* Kb = g_K + (size_t)bh * (SEQ * HD);
    const float* Vb = g_V + (size_t)bh * (SEQ * HD);

    ull q2[32];
    {
        const float4* qp = (const float4*)(Qb + (size_t)qrow * HD);
        #pragma unroll
        for (int i = 0; i < 16; i++) {
            float4 v = qp[i];
            q2[2*i]   = pack2(v.x * 0.125f, v.y * 0.125f);
            q2[2*i+1] = pack2(v.z * 0.125f, v.w * 0.125f);
        }
    }

    ull o2[32];
    #pragma unroll
    for (int i = 0; i < 32; i++) o2[i] = 0ull;
    float m = -1e30f, l = 0.0f;

    #pragma unroll 1
    for (int kt = 0; kt < SEQ / 32; ++kt) {
        {
            const float4* ksrc = (const float4*)(Kb + (size_t)kt * 32 * HD);
            const float4* vsrc = (const float4*)(Vb + (size_t)kt * 32 * HD);
            float4* kdst = (float4*)&Ks[0][0];
            float4* vdst = (float4*)&Vs[0][0];
            #pragma unroll
            for (int i = 0; i < 4; i++) {
                kdst[tid + 128 * i] = ksrc[tid + 128 * i];
                vdst[tid + 128 * i] = vsrc[tid + 128 * i];
            }
        }
        __syncthreads();

        float s[32];
        #pragma unroll
        for (int j = 0; j < 32; j++) {
            const float4* kp = (const float4*)&Ks[j][0];
            ull a0 = 0, a1 = 0, a2 = 0, a3 = 0;
            #pragma unroll
            for (int i = 0; i < 4; i++) {
                F4U2 t0, t1, t2, t3;
                t0.f4 = kp[4*i+0]; t1.f4 = kp[4*i+1];
                t2.f4 = kp[4*i+2]; t3.f4 = kp[4*i+3];
                a0 = ffma2(q2[8*i+0], t0.u[0], a0);
                a1 = ffma2(q2[8*i+1], t0.u[1], a1);
                a2 = ffma2(q2[8*i+2], t1.u[0], a2);
                a3 = ffma2(q2[8*i+3], t1.u[1], a3);
                a0 = ffma2(q2[8*i+4], t2.u[0], a0);
                a1 = ffma2(q2[8*i+5], t2.u[1], a1);
                a2 = ffma2(q2[8*i+6], t3.u[0], a2);
                a3 = ffma2(q2[8*i+7], t3.u[1], a3);
            }
            float2 r0 = unpack2(a0), r1 = unpack2(a1);
            float2 r2 = unpack2(a2), r3 = unpack2(a3);
            s[j] = ((r0.x + r0.y) + (r1.x + r1.y)) + ((r2.x + r2.y) + (r3.x + r3.y));
        }

        float mt = m;
        #pragma unroll
        for (int j = 0; j < 32; j++) mt = fmaxf(mt, s[j]);
        float corr = __expf(m - mt);
        m = mt;
        l *= corr;
        ull c2 = pack2(corr, corr);
        #pragma unroll
        for (int i = 0; i < 32; i++) o2[i] = fmul2(o2[i], c2);

        #pragma unroll
        for (int j = 0; j < 32; j++) {
            float p = __expf(s[j] - m);
            l += p;
            ull p2 = pack2(p, p);
            const float4* vp = (const float4*)&Vs[j][0];
            #pragma unroll
            for (int i = 0; i < 8; i++) {
                F4U2 t0, t1;
                t0.f4 = vp[2*i]; t1.f4 = vp[2*i+1];
                o2[4*i+0] = ffma2(p2, t0.u[0], o2[4*i+0]);
                o2[4*i+1] = ffma2(p2, t0.u[1], o2[4*i+1]);
                o2[4*i+2] = ffma2(p2, t1.u[0], o2[4*i+2]);
                o2[4*i+3] = ffma2(p2, t1.u[1], o2[4*i+3]);
            }
        }
        __syncthreads();
    }

    // write split-bf16 output in [B, N, H*D] layout
    float inv = 1.0f / l;
    int b = bh >> 4;
    int h = bh & 15;
    size_t obase = ((size_t)(b * SEQ + qrow)) * CDIM + h * HD;
    #pragma unroll
    for (int i = 0; i < 8; i++) {
        float vals[8];
        #pragma unroll
        for (int k = 0; k < 4; k++) {
            float2 v = unpack2(o2[4*i+k]);
            vals[2*k]   = v.x * inv;
            vals[2*k+1] = v.y * inv;
        }
        union { uint4 u4; __nv_bfloat16 hh[8]; } ph, pl;
        #pragma unroll
        for (int k = 0; k < 8; k++) {
            __nv_bfloat16 hv = __float2bfloat16(vals[k]);
            ph.hh[k] = hv;
            pl.hh[k] = __float2bfloat16(vals[k] - __bfloat162float(hv));
        }
        *(uint4*)&g_Ohi[obase + 8*i] = ph.u4;
        *(uint4*)&g_Olo[obase + 8*i] = pl.u4;
    }
}

// ---------------- launch ----------------
extern "C" void kernel_launch(void* const* d_in, const int* in_sizes, int n_in,
                              void* d_out, int out_size)
{
    const float* x      = (const float*)d_in[0];
    const float* W_qkv  = (const float*)d_in[1];
    const float* b_qkv  = (const float*)d_in[2];
    const float* W_proj = (const float*)d_in[3];
    const float* b_proj = (const float*)d_in[4];
    float* out = (float*)d_out;

    // 1) split x -> g_Ahi/g_Alo
    conv_split<<<(MROWS * KDIM / 4 + 255) / 256, 256>>>(x, MROWS * KDIM / 4);

    // 2) transpose+split weights
    {
        dim3 bdim(32, 8);
        dim3 gq(NQKV / 32, KDIM / 32);
        conv_wT<0><<<gq, bdim>>>(W_qkv, NQKV);
        dim3 gp(CDIM / 32, KDIM / 32);
        conv_wT<1><<<gp, bdim>>>(W_proj, CDIM);
    }

    // 3) QKV GEMM (HMMA) + scatter
    {
        dim3 g(NQKV / 128, MROWS / 128);   // (24, 64)
        mma_gemm<0><<<g, 256>>>(b_qkv, nullptr);
    }

    // 4) attention (fp32 SIMT), writes split-bf16 O
    {
        dim3 ga(SEQ / 128, BB * NH);
        attn_kernel<<<ga, 128>>>();
    }

    // 5) proj GEMM (HMMA)
    {
        dim3 g(CDIM / 128, MROWS / 128);   // (8, 64)
        mma_gemm<1><<<g, 256>>>(b_proj, out);
    }
}

// round 4
// speedup vs baseline: 1.2828x; 1.0009x over previous
#include <cuda_runtime.h>
#include <cuda_bf16.h>
#include <cstdint>
#include <math.h>

// ---------------- problem constants ----------------
#define BB   4
#define SEQ  2048
#define CDIM 1024
#define NH   16
#define HD   64
#define MROWS (BB*SEQ)          // 8192
#define KDIM 1024
#define NQKV 3072
#define BK   32
#define PADK 40                 // padded smem row (bf16 elems): conflict-free ldmatrix
#define NCHUNK 96               // K' = 3*1024 / 32

// ---------------- scratch (device globals) ----------------
__device__ float g_Q[BB*NH*SEQ*HD];   // [B,H,N,D] fp32
__device__ float g_K[BB*NH*SEQ*HD];
__device__ float g_V[BB*NH*SEQ*HD];
__device__ __nv_bfloat16 g_Ahi[MROWS*KDIM];
__device__ __nv_bfloat16 g_Alo[MROWS*KDIM];
__device__ __nv_bfloat16 g_Ohi[MROWS*CDIM];   // attention out split, [B,N,H*D]
__device__ __nv_bfloat16 g_Olo[MROWS*CDIM];
__device__ __nv_bfloat16 g_Wqhi[NQKV*KDIM];   // W_qkv^T split, [N,K]
__device__ __nv_bfloat16 g_Wqlo[NQKV*KDIM];
__device__ __nv_bfloat16 g_Wphi[CDIM*KDIM];   // W_proj^T split, [N,K]
__device__ __nv_bfloat16 g_Wplo[CDIM*KDIM];

// ---------------- helpers ----------------
typedef unsigned long long ull;

__device__ __forceinline__ uint32_t smem_u32(const void* p) {
    return (uint32_t)__cvta_generic_to_shared(p);
}
__device__ __forceinline__ ull ffma2(ull a, ull b, ull c) {
    ull d; asm("fma.rn.f32x2 %0, %1, %2, %3;" : "=l"(d) : "l"(a), "l"(b), "l"(c)); return d;
}
__device__ __forceinline__ ull fmul2(ull a, ull b) {
    ull d; asm("mul.rn.f32x2 %0, %1, %2;" : "=l"(d) : "l"(a), "l"(b)); return d;
}
__device__ __forceinline__ ull pack2(float lo, float hi) {
    ull r; asm("mov.b64 %0, {%1, %2};" : "=l"(r) : "f"(lo), "f"(hi)); return r;
}
__device__ __forceinline__ float2 unpack2(ull v) {
    float lo, hi; asm("mov.b64 {%0, %1}, %2;" : "=f"(lo), "=f"(hi) : "l"(v));
    return make_float2(lo, hi);
}
union F4U2 { float4 f4; ull u[2]; };

__device__ __forceinline__ void cp16(uint32_t dst, const void* src) {
    asm volatile("cp.async.cg.shared.global [%0], [%1], 16;" :: "r"(dst), "l"(src));
}
__device__ __forceinline__ void cp_commit() {
    asm volatile("cp.async.commit_group;");
}
__device__ __forceinline__ void ldm_x4(uint32_t* r, uint32_t addr) {
    asm volatile("ldmatrix.sync.aligned.m8n8.x4.shared.b16 {%0,%1,%2,%3}, [%4];"
                 : "=r"(r[0]), "=r"(r[1]), "=r"(r[2]), "=r"(r[3]) : "r"(addr));
}
__device__ __forceinline__ void mma16816(float* c, const uint32_t* a, const uint32_t* b) {
    asm volatile(
        "mma.sync.aligned.m16n8k16.row.col.f32.bf16.bf16.f32 "
        "{%0,%1,%2,%3}, {%4,%5,%6,%7}, {%8,%9}, {%0,%1,%2,%3};"
        : "+f"(c[0]), "+f"(c[1]), "+f"(c[2]), "+f"(c[3])
        : "r"(a[0]), "r"(a[1]), "r"(a[2]), "r"(a[3]), "r"(b[0]), "r"(b[1]));
}

// ---------------- conversion kernels (write fixed globals) ----------------
__global__ void conv_split(const float* __restrict__ src, int n4)
{
    int i = blockIdx.x * blockDim.x + threadIdx.x;
    if (i >= n4) return;
    float4 v = ((const float4*)src)[i];
    union { uint2 u; __nv_bfloat16 h[4]; } ph, pl;
    float vv[4] = { v.x, v.y, v.z, v.w };
    #pragma unroll
    for (int k = 0; k < 4; k++) {
        __nv_bfloat16 h = __float2bfloat16(vv[k]);
        ph.h[k] = h;
        pl.h[k] = __float2bfloat16(vv[k] - __bfloat162float(h));
    }
    ((uint2*)g_Ahi)[i] = ph.u;
    ((uint2*)g_Alo)[i] = pl.u;
}

// transpose + split: W[K,N] row-major -> [N,K]; SEL 0 -> Wq, 1 -> Wp
template <int SEL>
__global__ void conv_wT(const float* __restrict__ W, int Nd)
{
    __shared__ float t[32][33];
    __nv_bfloat16* hi = SEL ? g_Wphi : g_Wqhi;
    __nv_bfloat16* lo = SEL ? g_Wplo : g_Wqlo;
    int n0 = blockIdx.x * 32, k0 = blockIdx.y * 32;
    #pragma unroll
    for (int i = 0; i < 4; i++) {
        int k = k0 + threadIdx.y + i * 8;
        t[threadIdx.y + i * 8][threadIdx.x] = W[(size_t)k * Nd + n0 + threadIdx.x];
    }
    __syncthreads();
    #pragma unroll
    for (int i = 0; i < 4; i++) {
        int n = n0 + threadIdx.y + i * 8;
        int k = k0 + threadIdx.x;
        float v = t[threadIdx.x][threadIdx.y + i * 8];
        __nv_bfloat16 h = __float2bfloat16(v);
        hi[(size_t)n * KDIM + k] = h;
        lo[(size_t)n * KDIM + k] = __float2bfloat16(v - __bfloat162float(h));
    }
}

// ---------------- split-bf16 GEMM on mma.sync (HMMA) ----------------
// C[M,N] = A[M,K] x B[N,K]^T, K' = 3K via segments (AhiBhi + AloBhi + AhiBlo).
// 128x128 tile, BK=32, 8 warps (2 M x 4 N), warp tile 64x32.
// MODE 0: A = x split, B = Wq split, scatter to g_Q/K/V + b_qkv.
// MODE 1: A = O split, B = Wp split, write out + b_proj.
template <int MODE>
__global__ __launch_bounds__(256)
void mma_gemm(const float* __restrict__ bias, float* __restrict__ out)
{
    constexpr int Ndim = (MODE == 0) ? NQKV : CDIM;
    __shared__ __align__(16) __nv_bfloat16 As[2][128 * PADK];
    __shared__ __align__(16) __nv_bfloat16 Bs[2][128 * PADK];

    const __nv_bfloat16* Ahi = (MODE == 0) ? g_Ahi : g_Ohi;
    const __nv_bfloat16* Alo = (MODE == 0) ? g_Alo : g_Olo;
    const __nv_bfloat16* Bhi = (MODE == 0) ? g_Wqhi : g_Wphi;
    const __nv_bfloat16* Blo = (MODE == 0) ? g_Wqlo : g_Wplo;

    const int tid = threadIdx.x;
    const int lane = tid & 31, wid = tid >> 5;
    const int warp_m = wid >> 2, warp_n = wid & 3;
    const int mTile = blockIdx.y, nTile = blockIdx.x;
    const int aRow0 = mTile * 128, bRow0 = nTile * 128;

    const int lrow = tid >> 2;   // 0..63
    const int lseg = tid & 3;    // 0..3

    const uint32_t asBase = smem_u32(&As[0][0]);
    const uint32_t bsBase = smem_u32(&Bs[0][0]);
    const uint32_t stageBytes = 128 * PADK * 2;

    auto load_chunk = [&](int kc) {
        int seg = kc >> 5;
        int k0  = (kc & 31) * BK;
        const __nv_bfloat16* Ap = (seg == 1) ? Alo : Ahi;
        const __nv_bfloat16* Bp = (seg == 2) ? Blo : Bhi;
        uint32_t so = (uint32_t)(kc & 1) * stageBytes;
        #pragma unroll
        for (int i = 0; i < 2; i++) {
            int row = lrow + 64 * i;
            uint32_t doff = so + (uint32_t)row * (PADK * 2) + (uint32_t)lseg * 16;
            cp16(asBase + doff, Ap + (size_t)(aRow0 + row) * KDIM + k0 + lseg * 8);
            cp16(bsBase + doff, Bp + (size_t)(bRow0 + row) * KDIM + k0 + lseg * 8);
        }
        cp_commit();
    };

    float acc[4][4][4];
    #pragma unroll
    for (int mi = 0; mi < 4; mi++)
        #pragma unroll
        for (int ni = 0; ni < 4; ni++)
            #pragma unroll
            for (int q = 0; q < 4; q++) acc[mi][ni][q] = 0.0f;

    load_chunk(0);
    load_chunk(1);

    // per-thread ldmatrix relative offsets
    const int aRowL = warp_m * 64 + (lane & 15);
    const int aKoff = (lane >> 4) << 3;
    const int bRowL = warp_n * 32 + ((lane >> 4) << 3) + (lane & 7);
    const int bKoff = ((lane >> 3) & 1) << 3;

    #pragma unroll 1
    for (int kc = 0; kc < NCHUNK; ++kc) {
        if (kc == NCHUNK - 1) asm volatile("cp.async.wait_group 0;" ::: "memory");
        else                  asm volatile("cp.async.wait_group 1;" ::: "memory");
        __syncthreads();

        uint32_t ab = asBase + (uint32_t)(kc & 1) * stageBytes;
        uint32_t bb = bsBase + (uint32_t)(kc & 1) * stageBytes;

        #pragma unroll
        for (int ks = 0; ks < 2; ks++) {
            uint32_t a_r[4][4];
            uint32_t b_r[4][2];
            #pragma unroll
            for (int mi = 0; mi < 4; mi++) {
                uint32_t addr = ab + (uint32_t)(aRowL + mi * 16) * (PADK * 2)
                              + (uint32_t)(ks * 16 + aKoff) * 2;
                ldm_x4(a_r[mi], addr);
            }
            #pragma unroll
            for (int np = 0; np < 2; np++) {
                uint32_t addr = bb + (uint32_t)(bRowL + np * 16) * (PADK * 2)
                              + (uint32_t)(ks * 16 + bKoff) * 2;
                uint32_t r[4];
                ldm_x4(r, addr);
                b_r[np * 2][0]     = r[0];
                b_r[np * 2][1]     = r[1];
                b_r[np * 2 + 1][0] = r[2];
                b_r[np * 2 + 1][1] = r[3];
            }
            #pragma unroll
            for (int mi = 0; mi < 4; mi++)
                #pragma unroll
                for (int ni = 0; ni < 4; ni++)
                    mma16816(acc[mi][ni], a_r[mi], b_r[ni]);
        }
        __syncthreads();
        if (kc + 2 < NCHUNK) load_chunk(kc + 2);
    }

    // ---------------- epilogue ----------------
    const int mBase = mTile * 128 + warp_m * 64;
    const int nBase = nTile * 128 + warp_n * 32;
    const int rq = lane >> 2;
    const int cq = (lane & 3) * 2;

    #pragma unroll
    for (int mi = 0; mi < 4; mi++) {
        #pragma unroll
        for (int ni = 0; ni < 4; ni++) {
            int col = nBase + ni * 8 + cq;
            float2 bv = *(const float2*)&bias[col];
            #pragma unroll
            for (int h2 = 0; h2 < 2; h2++) {
                int row = mBase + mi * 16 + rq + h2 * 8;
                float2 v = make_float2(acc[mi][ni][h2 * 2]     + bv.x,
                                       acc[mi][ni][h2 * 2 + 1] + bv.y);
                if (MODE == 0) {
                    int part = col >> 10;
                    float* dst = (part == 0) ? g_Q : (part == 1) ? g_K : g_V;
                    int b = row >> 11, n = row & 2047;
                    int h = (col & 1023) >> 6, d = col & 63;
                    *(float2*)&dst[(((size_t)(b * NH + h)) * SEQ + n) * HD + d] = v;
                } else {
                    *(float2*)&out[(size_t)row * Ndim + col] = v;
                }
            }
        }
    }
}

// ---------------- flash attention (fp32 SIMT; split-bf16 output) ----------
__global__ __launch_bounds__(128, 2)
void attn_kernel()
{
    __shared__ __align__(16) float Ks[32][64];
    __shared__ __align__(16) float Vs[32][64];

    const int tid  = threadIdx.x;
    const int bh   = blockIdx.y;
    const int qrow = blockIdx.x * 128 + tid;

    const float* Qb = g_Q + (size_t)bh * (SEQ * HD);
    const float* Kb = g_K + (size_t)bh * (SEQ * HD);
    const float* Vb = g_V + (size_t)bh * (SEQ * HD);

    ull q2[32];
    {
        const float4* qp = (const float4*)(Qb + (size_t)qrow * HD);
        #pragma unroll
        for (int i = 0; i < 16; i++) {
            float4 v = qp[i];
            q2[2*i]   = pack2(v.x * 0.125f, v.y * 0.125f);
            q2[2*i+1] = pack2(v.z * 0.125f, v.w * 0.125f);
        }
    }

    ull o2[32];
    #pragma unroll
    for (int i = 0; i < 32; i++) o2[i] = 0ull;
    float m = -1e30f, l = 0.0f;

    #pragma unroll 1
    for (int kt = 0; kt < SEQ / 32; ++kt) {
        {
            const float4* ksrc = (const float4*)(Kb + (size_t)kt * 32 * HD);
            const float4* vsrc = (const float4*)(Vb + (size_t)kt * 32 * HD);
            float4* kdst = (float4*)&Ks[0][0];
            float4* vdst = (float4*)&Vs[0][0];
            #pragma unroll
            for (int i = 0; i < 4; i++) {
                kdst[tid + 128 * i] = ksrc[tid + 128 * i];
                vdst[tid + 128 * i] = vsrc[tid + 128 * i];
            }
        }
        __syncthreads();

        float s[32];
        #pragma unroll
        for (int j = 0; j < 32; j++) {
            const float4* kp = (const float4*)&Ks[j][0];
            ull a0 = 0, a1 = 0, a2 = 0, a3 = 0;
            #pragma unroll
            for (int i = 0; i < 4; i++) {
                F4U2 t0, t1, t2, t3;
                t0.f4 = kp[4*i+0]; t1.f4 = kp[4*i+1];
                t2.f4 = kp[4*i+2]; t3.f4 = kp[4*i+3];
                a0 = ffma2(q2[8*i+0], t0.u[0], a0);
                a1 = ffma2(q2[8*i+1], t0.u[1], a1);
                a2 = ffma2(q2[8*i+2], t1.u[0], a2);
                a3 = ffma2(q2[8*i+3], t1.u[1], a3);
                a0 = ffma2(q2[8*i+4], t2.u[0], a0);
                a1 = ffma2(q2[8*i+5], t2.u[1], a1);
                a2 = ffma2(q2[8*i+6], t3.u[0], a2);
                a3 = ffma2(q2[8*i+7], t3.u[1], a3);
            }
            float2 r0 = unpack2(a0), r1 = unpack2(a1);
            float2 r2 = unpack2(a2), r3 = unpack2(a3);
            s[j] = ((r0.x + r0.y) + (r1.x + r1.y)) + ((r2.x + r2.y) + (r3.x + r3.y));
        }

        float mt = m;
        #pragma unroll
        for (int j = 0; j < 32; j++) mt = fmaxf(mt, s[j]);
        float corr = __expf(m - mt);
        m = mt;
        l *= corr;
        ull c2 = pack2(corr, corr);
        #pragma unroll
        for (int i = 0; i < 32; i++) o2[i] = fmul2(o2[i], c2);

        #pragma unroll
        for (int j = 0; j < 32; j++) {
            float p = __expf(s[j] - m);
            l += p;
            ull p2 = pack2(p, p);
            const float4* vp = (const float4*)&Vs[j][0];
            #pragma unroll
            for (int i = 0; i < 8; i++) {
                F4U2 t0, t1;
                t0.f4 = vp[2*i]; t1.f4 = vp[2*i+1];
                o2[4*i+0] = ffma2(p2, t0.u[0], o2[4*i+0]);
                o2[4*i+1] = ffma2(p2, t0.u[1], o2[4*i+1]);
                o2[4*i+2] = ffma2(p2, t1.u[0], o2[4*i+2]);
                o2[4*i+3] = ffma2(p2, t1.u[1], o2[4*i+3]);
            }
        }
        __syncthreads();
    }

    // write split-bf16 output in [B, N, H*D] layout
    float inv = 1.0f / l;
    int b = bh >> 4;
    int h = bh & 15;
    size_t obase = ((size_t)(b * SEQ + qrow)) * CDIM + h * HD;
    #pragma unroll
    for (int i = 0; i < 8; i++) {
        float vals[8];
        #pragma unroll
        for (int k = 0; k < 4; k++) {
            float2 v = unpack2(o2[4*i+k]);
            vals[2*k]   = v.x * inv;
            vals[2*k+1] = v.y * inv;
        }
        union { uint4 u4; __nv_bfloat16 hh[8]; } ph, pl;
        #pragma unroll
        for (int k = 0; k < 8; k++) {
            __nv_bfloat16 hv = __float2bfloat16(vals[k]);
            ph.hh[k] = hv;
            pl.hh[k] = __float2bfloat16(vals[k] - __bfloat162float(hv));
        }
        *(uint4*)&g_Ohi[obase + 8*i] = ph.u4;
        *(uint4*)&g_Olo[obase + 8*i] = pl.u4;
    }
}

// ---------------- launch ----------------
extern "C" void kernel_launch(void* const* d_in, const int* in_sizes, int n_in,
                              void* d_out, int out_size)
{
    const float* x      = (const float*)d_in[0];
    const float* W_qkv  = (const float*)d_in[1];
    const float* b_qkv  = (const float*)d_in[2];
    const float* W_proj = (const float*)d_in[3];
    const float* b_proj = (const float*)d_in[4];
    float* out = (float*)d_out;

    // 1) split x -> g_Ahi/g_Alo
    conv_split<<<(MROWS * KDIM / 4 + 255) / 256, 256>>>(x, MROWS * KDIM / 4);

    // 2) transpose+split weights
    {
        dim3 bdim(32, 8);
        dim3 gq(NQKV / 32, KDIM / 32);
        conv_wT<0><<<gq, bdim>>>(W_qkv, NQKV);
        dim3 gp(CDIM / 32, KDIM / 32);
        conv_wT<1><<<gp, bdim>>>(W_proj, CDIM);
    }

    // 3) QKV GEMM (HMMA) + scatter
    {
        dim3 g(NQKV / 128, MROWS / 128);   // (24, 64)
        mma_gemm<0><<<g, 256>>>(b_qkv, nullptr);
    }

    // 4) attention (fp32 SIMT), writes split-bf16 O
    {
        dim3 ga(SEQ / 128, BB * NH);
        attn_kernel<<<ga, 128>>>();
    }

    // 5) proj GEMM (HMMA)
    {
        dim3 g(CDIM / 128, MROWS / 128);   // (8, 64)
        mma_gemm<1><<<g, 256>>>(b_proj, out);
    }
}

// round 5
// speedup vs baseline: 2.5310x; 1.9729x over previous
#include <cuda_runtime.h>
#include <cuda_bf16.h>
#include <cstdint>
#include <math.h>

#define BB   4
#define SEQ  2048
#define CDIM 1024
#define NH   16
#define HD   64
#define MROWS (BB*SEQ)
#define KDIM 1024
#define NQKV 3072
#define BK   32
#define PADK 40
#define NCHUNK 96

#define PADA 136                          // attn smem row: 128 data + 8 pad (bf16)
#define ROWB (PADA*2)                     // 272 bytes
#define QSMEM_BYTES (128*ROWB)            // 34816
#define KVSTRIDE    (64*ROWB)             // 17408
#define KVBUF       (2*KVSTRIDE)          // 34816
#define ATTN_SMEM   (QSMEM_BYTES + 2*KVBUF)  // 104448

#define QSCALE 0.1803368801111179f        // 0.125 * log2(e)

// ---------------- scratch ----------------
__device__ __nv_bfloat16 g_Qhi[BB*NH*SEQ*HD];  // [B,H,N,D], pre-scaled
__device__ __nv_bfloat16 g_Qlo[BB*NH*SEQ*HD];
__device__ __nv_bfloat16 g_Khi[BB*NH*SEQ*HD];
__device__ __nv_bfloat16 g_Klo[BB*NH*SEQ*HD];
__device__ __nv_bfloat16 g_Vhi[BB*NH*SEQ*HD];
__device__ __nv_bfloat16 g_Vlo[BB*NH*SEQ*HD];
__device__ __nv_bfloat16 g_Ahi[MROWS*KDIM];
__device__ __nv_bfloat16 g_Alo[MROWS*KDIM];
__device__ __nv_bfloat16 g_Ohi[MROWS*CDIM];    // [B,N,H*D]
__device__ __nv_bfloat16 g_Olo[MROWS*CDIM];
__device__ __nv_bfloat16 g_Wqhi[NQKV*KDIM];
__device__ __nv_bfloat16 g_Wqlo[NQKV*KDIM];
__device__ __nv_bfloat16 g_Wphi[CDIM*KDIM];
__device__ __nv_bfloat16 g_Wplo[CDIM*KDIM];

// ---------------- helpers ----------------
typedef unsigned long long ull;

__device__ __forceinline__ uint32_t smem_u32(const void* p) {
    return (uint32_t)__cvta_generic_to_shared(p);
}
__device__ __forceinline__ ull ffma2(ull a, ull b, ull c) {
    ull d; asm("fma.rn.f32x2 %0, %1, %2, %3;" : "=l"(d) : "l"(a), "l"(b), "l"(c)); return d;
}
__device__ __forceinline__ ull add2(ull a, ull b) {
    ull d; asm("add.rn.f32x2 %0, %1, %2;" : "=l"(d) : "l"(a), "l"(b)); return d;
}
__device__ __forceinline__ ull pack2(float lo, float hi) {
    ull r; asm("mov.b64 %0, {%1, %2};" : "=l"(r) : "f"(lo), "f"(hi)); return r;
}
__device__ __forceinline__ float2 unpack2(ull v) {
    float lo, hi; asm("mov.b64 {%0, %1}, %2;" : "=f"(lo), "=f"(hi) : "l"(v));
    return make_float2(lo, hi);
}
__device__ __forceinline__ void cp16(uint32_t dst, const void* src) {
    asm volatile("cp.async.cg.shared.global [%0], [%1], 16;" :: "r"(dst), "l"(src));
}
__device__ __forceinline__ void cp_commit() { asm volatile("cp.async.commit_group;"); }
__device__ __forceinline__ void ldm_x4(uint32_t* r, uint32_t addr) {
    asm volatile("ldmatrix.sync.aligned.m8n8.x4.shared.b16 {%0,%1,%2,%3}, [%4];"
                 : "=r"(r[0]), "=r"(r[1]), "=r"(r[2]), "=r"(r[3]) : "r"(addr));
}
__device__ __forceinline__ void ldm_x4_t(uint32_t* r, uint32_t addr) {
    asm volatile("ldmatrix.sync.aligned.m8n8.x4.trans.shared.b16 {%0,%1,%2,%3}, [%4];"
                 : "=r"(r[0]), "=r"(r[1]), "=r"(r[2]), "=r"(r[3]) : "r"(addr));
}
__device__ __forceinline__ void mma16816(float* c, const uint32_t* a, const uint32_t* b) {
    asm volatile(
        "mma.sync.aligned.m16n8k16.row.col.f32.bf16.bf16.f32 "
        "{%0,%1,%2,%3}, {%4,%5,%6,%7}, {%8,%9}, {%0,%1,%2,%3};"
        : "+f"(c[0]), "+f"(c[1]), "+f"(c[2]), "+f"(c[3])
        : "r"(a[0]), "r"(a[1]), "r"(a[2]), "r"(a[3]), "r"(b[0]), "r"(b[1]));
}
__device__ __forceinline__ void split_store(__nv_bfloat16* hiA, __nv_bfloat16* loA,
                                            size_t idx, float v0, float v1) {
    __nv_bfloat16 h0 = __float2bfloat16(v0), h1 = __float2bfloat16(v1);
    union { uint32_t u; __nv_bfloat16 h[2]; } ph, pl;
    ph.h[0] = h0; ph.h[1] = h1;
    pl.h[0] = __float2bfloat16(v0 - __bfloat162float(h0));
    pl.h[1] = __float2bfloat16(v1 - __bfloat162float(h1));
    *(uint32_t*)&hiA[idx] = ph.u;
    *(uint32_t*)&loA[idx] = pl.u;
}

// exp2 of a packed f32x2, entirely on FMA/ALU pipes
#define MAGICF 12582912.0f
__device__ __forceinline__ ull exp2pair(ull t) {
    const ull MAGIC2  = pack2(MAGICF, MAGICF);
    const ull NMAGIC2 = pack2(-MAGICF, -MAGICF);
    const ull NONE2   = pack2(-1.0f, -1.0f);
    const ull ONE2    = pack2(1.0f, 1.0f);
    const ull C1 = pack2(0.6931471805599453f, 0.6931471805599453f);
    const ull C2 = pack2(0.2402265069591007f, 0.2402265069591007f);
    const ull C3 = pack2(0.05550410866482158f, 0.05550410866482158f);
    const ull C4 = pack2(0.009618129107628477f, 0.009618129107628477f);
    const ull C5 = pack2(0.0013333558146428443f, 0.0013333558146428443f);
    ull m = add2(t, MAGIC2);
    ull kf = add2(m, NMAGIC2);
    ull f = ffma2(kf, NONE2, t);
    ull p = ffma2(C5, f, C4);
    p = ffma2(p, f, C3); p = ffma2(p, f, C2); p = ffma2(p, f, C1); p = ffma2(p, f, ONE2);
    float2 mf = unpack2(m); float2 pf = unpack2(p);
    uint32_t r0 = __float_as_uint(pf.x) + (__float_as_uint(mf.x) << 23);
    uint32_t r1 = __float_as_uint(pf.y) + (__float_as_uint(mf.y) << 23);
    return pack2(__uint_as_float(r0), __uint_as_float(r1));
}
__device__ __forceinline__ uint32_t hipack(float2 v) {
    return __byte_perm(__float_as_uint(v.x), __float_as_uint(v.y), 0x7632);
}
__device__ __forceinline__ uint32_t lopack(float2 v) {
    float la = v.x - __uint_as_float(__float_as_uint(v.x) & 0xFFFF0000u);
    float lb = v.y - __uint_as_float(__float_as_uint(v.y) & 0xFFFF0000u);
    uint32_t r; asm("cvt.rn.bf16x2.f32 %0, %1, %2;" : "=r"(r) : "f"(lb), "f"(la));
    return r;
}

// ---------------- conversion kernels ----------------
__global__ void conv_split(const float* __restrict__ src, int n4)
{
    int i = blockIdx.x * blockDim.x + threadIdx.x;
    if (i >= n4) return;
    float4 v = ((const float4*)src)[i];
    union { uint2 u; __nv_bfloat16 h[4]; } ph, pl;
    float vv[4] = { v.x, v.y, v.z, v.w };
    #pragma unroll
    for (int k = 0; k < 4; k++) {
        __nv_bfloat16 h = __float2bfloat16(vv[k]);
        ph.h[k] = h;
        pl.h[k] = __float2bfloat16(vv[k] - __bfloat162float(h));
    }
    ((uint2*)g_Ahi)[i] = ph.u;
    ((uint2*)g_Alo)[i] = pl.u;
}

template <int SEL>
__global__ void conv_wT(const float* __restrict__ W, int Nd)
{
    __shared__ float t[32][33];
    __nv_bfloat16* hi = SEL ? g_Wphi : g_Wqhi;
    __nv_bfloat16* lo = SEL ? g_Wplo : g_Wqlo;
    int n0 = blockIdx.x * 32, k0 = blockIdx.y * 32;
    #pragma unroll
    for (int i = 0; i < 4; i++) {
        int k = k0 + threadIdx.y + i * 8;
        t[threadIdx.y + i * 8][threadIdx.x] = W[(size_t)k * Nd + n0 + threadIdx.x];
    }
    __syncthreads();
    #pragma unroll
    for (int i = 0; i < 4; i++) {
        int n = n0 + threadIdx.y + i * 8;
        int k = k0 + threadIdx.x;
        float v = t[threadIdx.x][threadIdx.y + i * 8];
        __nv_bfloat16 h = __float2bfloat16(v);
        hi[(size_t)n * KDIM + k] = h;
        lo[(size_t)n * KDIM + k] = __float2bfloat16(v - __bfloat162float(h));
    }
}

// ---------------- split-bf16 GEMM on mma.sync ----------------
template <int MODE>
__global__ __launch_bounds__(256)
void mma_gemm(const float* __restrict__ bias, float* __restrict__ out)
{
    constexpr int Ndim = (MODE == 0) ? NQKV : CDIM;
    __shared__ __align__(16) __nv_bfloat16 As[2][128 * PADK];
    __shared__ __align__(16) __nv_bfloat16 Bs[2][128 * PADK];

    const __nv_bfloat16* Ahi = (MODE == 0) ? g_Ahi : g_Ohi;
    const __nv_bfloat16* Alo = (MODE == 0) ? g_Alo : g_Olo;
    const __nv_bfloat16* Bhi = (MODE == 0) ? g_Wqhi : g_Wphi;
    const __nv_bfloat16* Blo = (MODE == 0) ? g_Wqlo : g_Wplo;

    const int tid = threadIdx.x;
    const int lane = tid & 31, wid = tid >> 5;
    const int warp_m = wid >> 2, warp_n = wid & 3;
    const int mTile = blockIdx.y, nTile = blockIdx.x;
    const int aRow0 = mTile * 128, bRow0 = nTile * 128;
    const int lrow = tid >> 2, lseg = tid & 3;

    const uint32_t asBase = smem_u32(&As[0][0]);
    const uint32_t bsBase = smem_u32(&Bs[0][0]);
    const uint32_t stageBytes = 128 * PADK * 2;

    auto load_chunk = [&](int kc) {
        int seg = kc >> 5;
        int k0  = (kc & 31) * BK;
        const __nv_bfloat16* Ap = (seg == 1) ? Alo : Ahi;
        const __nv_bfloat16* Bp = (seg == 2) ? Blo : Bhi;
        uint32_t so = (uint32_t)(kc & 1) * stageBytes;
        #pragma unroll
        for (int i = 0; i < 2; i++) {
            int row = lrow + 64 * i;
            uint32_t doff = so + (uint32_t)row * (PADK * 2) + (uint32_t)lseg * 16;
            cp16(asBase + doff, Ap + (size_t)(aRow0 + row) * KDIM + k0 + lseg * 8);
            cp16(bsBase + doff, Bp + (size_t)(bRow0 + row) * KDIM + k0 + lseg * 8);
        }
        cp_commit();
    };

    float acc[4][4][4];
    #pragma unroll
    for (int mi = 0; mi < 4; mi++)
        #pragma unroll
        for (int ni = 0; ni < 4; ni++)
            #pragma unroll
            for (int q = 0; q < 4; q++) acc[mi][ni][q] = 0.0f;

    load_chunk(0);
    load_chunk(1);

    const int aRowL = warp_m * 64 + (lane & 15);
    const int aKoff = (lane >> 4) << 3;
    const int bRowL = warp_n * 32 + ((lane >> 4) << 3) + (lane & 7);
    const int bKoff = ((lane >> 3) & 1) << 3;

    #pragma unroll 1
    for (int kc = 0; kc < NCHUNK; ++kc) {
        if (kc == NCHUNK - 1) asm volatile("cp.async.wait_group 0;" ::: "memory");
        else                  asm volatile("cp.async.wait_group 1;" ::: "memory");
        __syncthreads();

        uint32_t ab = asBase + (uint32_t)(kc & 1) * stageBytes;
        uint32_t bb = bsBase + (uint32_t)(kc & 1) * stageBytes;

        #pragma unroll
        for (int ks = 0; ks < 2; ks++) {
            uint32_t a_r[4][4];
            uint32_t b_r[4][2];
            #pragma unroll
            for (int mi = 0; mi < 4; mi++)
                ldm_x4(a_r[mi], ab + (uint32_t)(aRowL + mi * 16) * (PADK * 2)
                                  + (uint32_t)(ks * 16 + aKoff) * 2);
            #pragma unroll
            for (int np = 0; np < 2; np++) {
                uint32_t r[4];
                ldm_x4(r, bb + (uint32_t)(bRowL + np * 16) * (PADK * 2)
                            + (uint32_t)(ks * 16 + bKoff) * 2);
                b_r[np*2][0] = r[0]; b_r[np*2][1] = r[1];
                b_r[np*2+1][0] = r[2]; b_r[np*2+1][1] = r[3];
            }
            #pragma unroll
            for (int mi = 0; mi < 4; mi++)
                #pragma unroll
                for (int ni = 0; ni < 4; ni++)
                    mma16816(acc[mi][ni], a_r[mi], b_r[ni]);
        }
        __syncthreads();
        if (kc + 2 < NCHUNK) load_chunk(kc + 2);
    }

    const int mBase = mTile * 128 + warp_m * 64;
    const int nBase = nTile * 128 + warp_n * 32;
    const int rq = lane >> 2, cq = (lane & 3) * 2;

    if (MODE == 0) {
        const int part = (nTile * 128) >> 10;
        __nv_bfloat16* hiA = (part == 0) ? g_Qhi : (part == 1) ? g_Khi : g_Vhi;
        __nv_bfloat16* loA = (part == 0) ? g_Qlo : (part == 1) ? g_Klo : g_Vlo;
        const float scl = (part == 0) ? QSCALE : 1.0f;
        #pragma unroll
        for (int mi = 0; mi < 4; mi++)
            #pragma unroll
            for (int ni = 0; ni < 4; ni++) {
                int col = nBase + ni * 8 + cq;
                float2 bv = *(const float2*)&bias[col];
                int h = (col & 1023) >> 6, d = col & 63;
                #pragma unroll
                for (int h2 = 0; h2 < 2; h2++) {
                    int row = mBase + mi * 16 + rq + h2 * 8;
                    int b = row >> 11, n = row & 2047;
                    size_t idx = (((size_t)(b * NH + h)) * SEQ + n) * HD + d;
                    split_store(hiA, loA, idx,
                                (acc[mi][ni][h2*2]   + bv.x) * scl,
                                (acc[mi][ni][h2*2+1] + bv.y) * scl);
                }
            }
    } else {
        #pragma unroll
        for (int mi = 0; mi < 4; mi++)
            #pragma unroll
            for (int ni = 0; ni < 4; ni++) {
                int col = nBase + ni * 8 + cq;
                float2 bv = *(const float2*)&bias[col];
                #pragma unroll
                for (int h2 = 0; h2 < 2; h2++) {
                    int row = mBase + mi * 16 + rq + h2 * 8;
                    float2 v = make_float2(acc[mi][ni][h2*2] + bv.x,
                                           acc[mi][ni][h2*2+1] + bv.y);
                    *(float2*)&out[(size_t)row * Ndim + col] = v;
                }
            }
    }
}

// ---------------- tensor-core flash attention ----------------
// grid (16, 64), 128 threads (4 warps), warp tile 32 q x 64 kv. No max; exp2 on FMA pipe.
__global__ __launch_bounds__(128)
void attn_mma()
{
    extern __shared__ char sm_[];
    const int tid  = threadIdx.x;
    const int lane = tid & 31, wid = tid >> 5;
    const int bh = blockIdx.y, qt = blockIdx.x;
    const int b = bh >> 4, h = bh & 15;

    const uint32_t QS  = smem_u32(sm_);
    const uint32_t KV0 = QS + QSMEM_BYTES;
    const size_t ghead = (size_t)bh * SEQ * HD;

    {   // Q tile: 128 rows x (64 hi | 64 lo)
        const __nv_bfloat16* qh = g_Qhi + ghead + ((size_t)qt * 128 + tid) * HD;
        const __nv_bfloat16* ql = g_Qlo + ghead + ((size_t)qt * 128 + tid) * HD;
        uint32_t dst = QS + (uint32_t)tid * ROWB;
        #pragma unroll
        for (int s = 0; s < 8; s++) {
            cp16(dst + s*16,       qh + s*8);
            cp16(dst + 128 + s*16, ql + s*8);
        }
        cp_commit();
    }

    auto load_kv = [&](int kt) {
        int r = tid >> 1, half = tid & 1;
        const size_t grow = ghead + ((size_t)kt * 64 + r) * HD;
        uint32_t kdst = KV0 + (uint32_t)(kt & 1) * KVBUF + (uint32_t)r * ROWB
                      + (uint32_t)half * 128;
        uint32_t vdst = kdst + KVSTRIDE;
        const __nv_bfloat16* ks = half ? (g_Klo + grow) : (g_Khi + grow);
        const __nv_bfloat16* vs = half ? (g_Vlo + grow) : (g_Vhi + grow);
        #pragma unroll
        for (int i = 0; i < 8; i++) {
            cp16(kdst + i*16, ks + i*8);
            cp16(vdst + i*16, vs + i*8);
        }
        cp_commit();
    };
    load_kv(0);
    load_kv(1);

    asm volatile("cp.async.wait_group 2;" ::: "memory");
    __syncthreads();

    // Qhi fragments cached in registers
    const int wrow = wid * 32;
    uint32_t qf[2][4][4];
    #pragma unroll
    for (int mi = 0; mi < 2; mi++) {
        uint32_t rowa = QS + (uint32_t)(wrow + mi*16 + (lane & 15)) * ROWB
                      + (uint32_t)((lane >> 4) << 4);
        #pragma unroll
        for (int k = 0; k < 4; k++) ldm_x4(qf[mi][k], rowa + k*32);
    }

    float oc[2][8][4];
    #pragma unroll
    for (int mi = 0; mi < 2; mi++)
        #pragma unroll
        for (int n = 0; n < 8; n++)
            #pragma unroll
            for (int q = 0; q < 4; q++) oc[mi][n][q] = 0.0f;
    ull lacc[2][2];
    lacc[0][0] = lacc[0][1] = lacc[1][0] = lacc[1][1] = pack2(0.0f, 0.0f);

    #pragma unroll 1
    for (int kt = 0; kt < SEQ/64; ++kt) {
        asm volatile("cp.async.wait_group 1;" ::: "memory");
        __syncthreads();

        const uint32_t Kb = KV0 + (uint32_t)(kt & 1) * KVBUF;
        const uint32_t Vb = Kb + KVSTRIDE;

        // S = Q.K^T, 3 segments (hi.hi, lo.hi, hi.lo)
        float sc[2][8][4];
        #pragma unroll
        for (int mi = 0; mi < 2; mi++)
            #pragma unroll
            for (int n = 0; n < 8; n++)
                #pragma unroll
                for (int q = 0; q < 4; q++) sc[mi][n][q] = 0.0f;

        #pragma unroll
        for (int ks = 0; ks < 12; ks++) {
            const int seg = ks >> 2, kk = ks & 3;
            const int bcol = ((seg == 2) ? 64 : 0) + kk * 16;
            uint32_t afl[2][4];
            if (seg == 1) {
                #pragma unroll
                for (int mi = 0; mi < 2; mi++)
                    ldm_x4(afl[mi], QS + (uint32_t)(wrow + mi*16 + (lane & 15)) * ROWB
                                      + (uint32_t)(64 + kk*16 + ((lane >> 4) << 3)) * 2);
            }
            uint32_t br[4][4];
            #pragma unroll
            for (int np = 0; np < 4; np++)
                ldm_x4(br[np], Kb + (uint32_t)(np*16 + ((lane >> 4) << 3) + (lane & 7)) * ROWB
                                 + (uint32_t)(bcol + (((lane >> 3) & 1) << 3)) * 2);
            #pragma unroll
            for (int mi = 0; mi < 2; mi++) {
                const uint32_t* a = (seg == 1) ? afl[mi] : qf[mi][kk];
                #pragma unroll
                for (int np = 0; np < 4; np++) {
                    mma16816(sc[mi][np*2],   a, &br[np][0]);
                    mma16816(sc[mi][np*2+1], a, &br[np][2]);
                }
            }
        }

        // exp2 + P split + PV, chunked by kk (16 kv each)
        #pragma unroll
        for (int kk = 0; kk < 4; kk++) {
            uint32_t aPhi[2][4], aPlo[2][4];
            #pragma unroll
            for (int mi = 0; mi < 2; mi++) {
                #pragma unroll
                for (int half = 0; half < 2; half++) {
                    int n = 2*kk + half;
                    ull p01 = exp2pair(pack2(sc[mi][n][0], sc[mi][n][1]));
                    ull p23 = exp2pair(pack2(sc[mi][n][2], sc[mi][n][3]));
                    lacc[mi][0] = add2(lacc[mi][0], p01);
                    lacc[mi][1] = add2(lacc[mi][1], p23);
                    float2 v01 = unpack2(p01), v23 = unpack2(p23);
                    aPhi[mi][half*2]   = hipack(v01);   // a0/a2: row r
                    aPhi[mi][half*2+1] = hipack(v23);   // a1/a3: row r+8
                    aPlo[mi][half*2]   = lopack(v01);
                    aPlo[mi][half*2+1] = lopack(v23);
                }
                // reorder to A-frag: a = {n0.c01, n0.c23, n1.c01, n1.c23} already matches:
                // a0=(r,k0-7), a1=(r+8,k0-7), a2=(r,k8-15), a3=(r+8,k8-15)
            }
            const uint32_t krow = (uint32_t)(kk*16 + ((lane >> 3) & 1) * 8 + (lane & 7));
            #pragma unroll
            for (int nb = 0; nb < 4; nb++) {
                uint32_t bhi[4], blo[4];
                ldm_x4_t(bhi, Vb + krow * ROWB + (uint32_t)(nb*16 + ((lane >> 4) << 3)) * 2);
                ldm_x4_t(blo, Vb + krow * ROWB + (uint32_t)(64 + nb*16 + ((lane >> 4) << 3)) * 2);
                #pragma unroll
                for (int mi = 0; mi < 2; mi++) {
                    mma16816(oc[mi][nb*2],   aPhi[mi], &bhi[0]);
                    mma16816(oc[mi][nb*2+1], aPhi[mi], &bhi[2]);
                    mma16816(oc[mi][nb*2],   aPlo[mi], &bhi[0]);
                    mma16816(oc[mi][nb*2+1], aPlo[mi], &bhi[2]);
                    mma16816(oc[mi][nb*2],   aPhi[mi], &blo[0]);
                    mma16816(oc[mi][nb*2+1], aPhi[mi], &blo[2]);
                }
            }
        }
        __syncthreads();
        if (kt + 2 < SEQ/64) load_kv(kt + 2);
    }

    // normalize + split-bf16 write to [B,N,H*D]
    #pragma unroll
    for (int mi = 0; mi < 2; mi++) {
        float2 L0 = unpack2(lacc[mi][0]);
        float l0 = L0.x + L0.y;
        l0 += __shfl_xor_sync(0xFFFFFFFFu, l0, 1);
        l0 += __shfl_xor_sync(0xFFFFFFFFu, l0, 2);
        float2 L1 = unpack2(lacc[mi][1]);
        float l1 = L1.x + L1.y;
        l1 += __shfl_xor_sync(0xFFFFFFFFu, l1, 1);
        l1 += __shfl_xor_sync(0xFFFFFFFFu, l1, 2);
        float inv0 = 1.0f / l0, inv1 = 1.0f / l1;
        int r0 = qt * 128 + wrow + mi*16 + (lane >> 2);
        #pragma unroll
        for (int ni = 0; ni < 8; ni++) {
            int d = ni*8 + (lane & 3)*2;
            size_t i0 = ((size_t)(b * SEQ + r0)) * CDIM + h * HD + d;
            size_t i1 = ((size_t)(b * SEQ + r0 + 8)) * CDIM + h * HD + d;
            split_store(g_Ohi, g_Olo, i0, oc[mi][ni][0]*inv0, oc[mi][ni][1]*inv0);
            split_store(g_Ohi, g_Olo, i1, oc[mi][ni][2]*inv1, oc[mi][ni][3]*inv1);
        }
    }
}

// ---------------- launch ----------------
extern "C" void kernel_launch(void* const* d_in, const int* in_sizes, int n_in,
                              void* d_out, int out_size)
{
    const float* x      = (const float*)d_in[0];
    const float* W_qkv  = (const float*)d_in[1];
    const float* b_qkv  = (const float*)d_in[2];
    const float* W_proj = (const float*)d_in[3];
    const float* b_proj = (const float*)d_in[4];
    float* out = (float*)d_out;

    cudaFuncSetAttribute(attn_mma, cudaFuncAttributeMaxDynamicSharedMemorySize, ATTN_SMEM);

    conv_split<<<(MROWS * KDIM / 4 + 255) / 256, 256>>>(x, MROWS * KDIM / 4);
    {
        dim3 bdim(32, 8);
        dim3 gq(NQKV / 32, KDIM / 32);
        conv_wT<0><<<gq, bdim>>>(W_qkv, NQKV);
        dim3 gp(CDIM / 32, KDIM / 32);
        conv_wT<1><<<gp, bdim>>>(W_proj, CDIM);
    }
    {
        dim3 g(NQKV / 128, MROWS / 128);
        mma_gemm<0><<<g, 256>>>(b_qkv, nullptr);
    }
    {
        dim3 ga(SEQ / 128, BB * NH);
        attn_mma<<<ga, 128, ATTN_SMEM>>>();
    }
    {
        dim3 g(CDIM / 128, MROWS / 128);
        mma_gemm<1><<<g, 256>>>(b_proj, out);
    }
}